// round 8
// baseline (speedup 1.0000x reference)
#include <cuda_runtime.h>
#include <cuda_bf16.h>
#include <cstdint>

// ---------------------------------------------------------------------------
// GraphAttentionLayer: N=4096, F=512, H=8, d=64
//  1) proj_kernel: Q/K/V = x @ W^T (bf16 mma), Q scaled by log2e/sqrt(512)
//  2) pack_kernel (32-reg grid-stride): adj -> bitmask (16 MB)
//  3) attn_kernel: flash attention, bitmask mask, 3-stage cp.async K/V,
//     fixed-max base-2 softmax, deferred l reduction.
// proj is launched FIRST (placed first), pack backfills on a LOW-priority
// stream; attn joins both. This inverts R7's placement order, which is why
// R7's fork/join failed to overlap.
// ---------------------------------------------------------------------------

#define NN 4096
#define FF 512
#define NH 8
#define HD 64

__device__ __nv_bfloat16 g_Q[NN * FF];
__device__ __nv_bfloat16 g_K[NN * FF];
__device__ __nv_bfloat16 g_V[NN * FF];
__device__ uint32_t g_mask[NH * NN * (NN / 32)];   // 16 MB

__device__ __forceinline__ uint32_t smem_u32(const void* p) {
    return (uint32_t)__cvta_generic_to_shared(p);
}

__device__ __forceinline__ void ldsm_x4(uint32_t addr, uint32_t& r0, uint32_t& r1,
                                        uint32_t& r2, uint32_t& r3) {
    asm volatile("ldmatrix.sync.aligned.m8n8.x4.shared.b16 {%0,%1,%2,%3}, [%4];"
                 : "=r"(r0), "=r"(r1), "=r"(r2), "=r"(r3) : "r"(addr));
}

__device__ __forceinline__ void ldsm_x4_t(uint32_t addr, uint32_t& r0, uint32_t& r1,
                                          uint32_t& r2, uint32_t& r3) {
    asm volatile("ldmatrix.sync.aligned.m8n8.x4.trans.shared.b16 {%0,%1,%2,%3}, [%4];"
                 : "=r"(r0), "=r"(r1), "=r"(r2), "=r"(r3) : "r"(addr));
}

__device__ __forceinline__ void mma16816(float* d, const uint32_t* a, uint32_t b0, uint32_t b1) {
    asm volatile("mma.sync.aligned.m16n8k16.row.col.f32.bf16.bf16.f32 "
                 "{%0,%1,%2,%3}, {%4,%5,%6,%7}, {%8,%9}, {%0,%1,%2,%3};"
                 : "+f"(d[0]), "+f"(d[1]), "+f"(d[2]), "+f"(d[3])
                 : "r"(a[0]), "r"(a[1]), "r"(a[2]), "r"(a[3]), "r"(b0), "r"(b1));
}

__device__ __forceinline__ uint32_t packbf(float lo, float hi) {
    uint32_t r;
    asm("cvt.rn.bf16x2.f32 %0, %1, %2;" : "=r"(r) : "f"(hi), "f"(lo));
    return r;
}

__device__ __forceinline__ float ex2(float x) {
    float r;
    asm("ex2.approx.ftz.f32 %0, %1;" : "=f"(r) : "f"(x));
    return r;
}

__device__ __forceinline__ void cp16(void* s, const void* g) {
    asm volatile("cp.async.cg.shared.global [%0], [%1], 16;"
                 :: "r"(smem_u32(s)), "l"(g));
}
__device__ __forceinline__ void cp_commit() { asm volatile("cp.async.commit_group;"); }
template <int n>
__device__ __forceinline__ void cp_wait() { asm volatile("cp.async.wait_group %0;" :: "n"(n)); }

// ---------------------------------------------------------------------------
// Pack adj -> bitmask. Own kernel: 32 regs, grid-stride, ~6.5 TB/s solo.
// ---------------------------------------------------------------------------
__global__ __launch_bounds__(256) void pack_kernel(const int* __restrict__ adj) {
    const int lane = threadIdx.x & 31;
    const int wg = (blockIdx.x * blockDim.x + threadIdx.x) >> 5;
    const int nw = (gridDim.x * blockDim.x) >> 5;
    const int grp = lane >> 3;
    const int shift = (lane & 7) * 4;
    const int total = NH * NN * (NN / 128);   // 1048576 tiles

    for (int T = wg * 2; T < total; T += nw * 2) {
#pragma unroll
        for (int u = 0; u < 2; ++u) {
            const int t = T + u;
            int4 v = __ldg((const int4*)(adj + (size_t)t * 128) + lane);
            uint32_t w = ((uint32_t)(v.x > 0) | ((uint32_t)(v.y > 0) << 1) |
                          ((uint32_t)(v.z > 0) << 2) | ((uint32_t)(v.w > 0) << 3)) << shift;
            w |= __shfl_xor_sync(0xffffffffu, w, 1);
            w |= __shfl_xor_sync(0xffffffffu, w, 2);
            w |= __shfl_xor_sync(0xffffffffu, w, 4);
            if ((lane & 7) == 0) g_mask[(size_t)t * 4 + grp] = w;
        }
    }
}

// ---------------------------------------------------------------------------
// Projection GEMM: tile 128x128x32, 256 threads. grid = (32, 12).
// ---------------------------------------------------------------------------
__global__ __launch_bounds__(256) void proj_kernel(const float* __restrict__ x,
                                                   const float* __restrict__ Wq,
                                                   const float* __restrict__ Wk,
                                                   const float* __restrict__ Wv) {
    __shared__ __nv_bfloat16 sA[128][40];
    __shared__ __nv_bfloat16 sB[128][40];

    const int tid = threadIdx.x;
    const int lane = tid & 31;
    const int warp = tid >> 5;
    const int wr = warp & 3;
    const int wc = warp >> 2;
    const int mblk = blockIdx.x;
    const int mat = blockIdx.y >> 2;
    const int nblk = blockIdx.y & 3;

    const float* W = (mat == 0) ? Wq : (mat == 1) ? Wk : Wv;
    __nv_bfloat16* dst = (mat == 0) ? g_Q : (mat == 1) ? g_K : g_V;
    // Q scale = 1/sqrt(512) * log2(e)   (softmax in base-2)
    const float scale = (mat == 0) ? (0.044194173824159216f * 1.4426950408889634f) : 1.0f;

    float acc[2][8][4];
#pragma unroll
    for (int mt = 0; mt < 2; ++mt)
#pragma unroll
        for (int t = 0; t < 8; ++t)
#pragma unroll
            for (int i = 0; i < 4; ++i) acc[mt][t][i] = 0.f;

    const int lr = tid >> 3;
    const int lc = (tid & 7) * 4;

    for (int kt = 0; kt < 16; ++kt) {
        const int k0 = kt * 32;
        __syncthreads();
#pragma unroll
        for (int p = 0; p < 4; ++p) {
            const int r = lr + p * 32;
            float4 av = *(const float4*)(x + (size_t)(mblk * 128 + r) * FF + k0 + lc);
            *(__nv_bfloat162*)&sA[r][lc]     = __floats2bfloat162_rn(av.x, av.y);
            *(__nv_bfloat162*)&sA[r][lc + 2] = __floats2bfloat162_rn(av.z, av.w);
            float4 bv = *(const float4*)(W + (size_t)(nblk * 128 + r) * FF + k0 + lc);
            *(__nv_bfloat162*)&sB[r][lc]     = __floats2bfloat162_rn(bv.x, bv.y);
            *(__nv_bfloat162*)&sB[r][lc + 2] = __floats2bfloat162_rn(bv.z, bv.w);
        }
        __syncthreads();

#pragma unroll
        for (int ks = 0; ks < 2; ++ks) {
            uint32_t af[2][4];
#pragma unroll
            for (int mt = 0; mt < 2; ++mt) {
                const int row = wr * 32 + mt * 16 + (lane & 7) + ((lane >> 3) & 1) * 8;
                const int col = ks * 16 + (lane >> 4) * 8;
                ldsm_x4(smem_u32(&sA[row][col]), af[mt][0], af[mt][1], af[mt][2], af[mt][3]);
            }
#pragma unroll
            for (int g = 0; g < 4; ++g) {
                const int row = wc * 64 + g * 16 + (lane & 7) + (lane >> 4) * 8;
                const int col = ks * 16 + ((lane >> 3) & 1) * 8;
                uint32_t b0, b1, b2, b3;
                ldsm_x4(smem_u32(&sB[row][col]), b0, b1, b2, b3);
#pragma unroll
                for (int mt = 0; mt < 2; ++mt) {
                    mma16816(acc[mt][2 * g],     af[mt], b0, b1);
                    mma16816(acc[mt][2 * g + 1], af[mt], b2, b3);
                }
            }
        }
    }

#pragma unroll
    for (int mt = 0; mt < 2; ++mt) {
        const int row = mblk * 128 + wr * 32 + mt * 16 + (lane >> 2);
#pragma unroll
        for (int t = 0; t < 8; ++t) {
            const int col = nblk * 128 + wc * 64 + t * 8 + (lane & 3) * 2;
            *(uint32_t*)&dst[(size_t)row * FF + col] =
                packbf(acc[mt][t][0] * scale, acc[mt][t][1] * scale);
            *(uint32_t*)&dst[(size_t)(row + 8) * FF + col] =
                packbf(acc[mt][t][2] * scale, acc[mt][t][3] * scale);
        }
    }
}

// ---------------------------------------------------------------------------
// Flash attention: bitmask masking, 3-stage cp.async K/V, fixed-max softmax.
// grid=(32,8), 256 threads (8 warps x 16 q rows), 2 CTAs/SM.
// Dynamic smem 55296 B: sK[3][64][72] bf16, sV[3][64][72] bf16.
// ---------------------------------------------------------------------------
#define ST_BYTES (64 * 72 * 2)
#define ATTN_SMEM (6 * ST_BYTES)

__global__ __launch_bounds__(256, 2) void attn_kernel(const float* __restrict__ x,
                                                      float* __restrict__ out) {
    extern __shared__ char sm[];
    __nv_bfloat16* sK = (__nv_bfloat16*)sm;                      // [3][64][72]
    __nv_bfloat16* sV = (__nv_bfloat16*)(sm + 3 * ST_BYTES);     // [3][64][72]

    const int tid = threadIdx.x;
    const int lane = tid & 31;
    const int warp = tid >> 5;
    const int q0 = blockIdx.x * 128;
    const int h = blockIdx.y;
    const int hc = h * HD;

    const int lr = tid >> 3;           // 0..31
    const int lc8 = (tid & 7) * 8;     // 0..56

    // --- stage Q (128 x 64, stride 72) through sK, grab frags ---
#pragma unroll
    for (int p = 0; p < 4; ++p) {
        const int r = lr + p * 32;
        uint4 v = *(const uint4*)(g_Q + (size_t)(q0 + r) * FF + hc + lc8);
        *(uint4*)&sK[r * 72 + lc8] = v;
    }
    __syncthreads();

    const int rw = warp * 16;
    uint32_t qf[4][4];
#pragma unroll
    for (int ks = 0; ks < 4; ++ks) {
        const int row = rw + (lane & 7) + ((lane >> 3) & 1) * 8;
        const int col = ks * 16 + (lane >> 4) * 8;
        ldsm_x4(smem_u32(&sK[row * 72 + col]), qf[ks][0], qf[ks][1], qf[ks][2], qf[ks][3]);
    }
    __syncthreads();

    float O[8][4];
#pragma unroll
    for (int t = 0; t < 8; ++t)
#pragma unroll
        for (int i = 0; i < 4; ++i) O[t][i] = 0.f;

    float l0 = 0.f, l1 = 0.f;          // per-lane partial sums (no running max)

    const int ci = lane & 3;
    const int rl0 = rw + (lane >> 2);
    const int r0g = q0 + rl0;
    const size_t mrow0 = ((size_t)h * NN + r0g) * (NN / 32);
    const size_t mrow1 = mrow0 + 8 * (NN / 32);

    // prologue: async-load tiles 0 and 1 into stages 0, 1
#pragma unroll
    for (int pre = 0; pre < 2; ++pre) {
        __nv_bfloat16* sKs = sK + pre * 64 * 72;
        __nv_bfloat16* sVs = sV + pre * 64 * 72;
#pragma unroll
        for (int p = 0; p < 2; ++p) {
            const int r = lr + p * 32;
            cp16(&sKs[r * 72 + lc8], g_K + (size_t)(pre * 64 + r) * FF + hc + lc8);
            cp16(&sVs[r * 72 + lc8], g_V + (size_t)(pre * 64 + r) * FF + hc + lc8);
        }
        cp_commit();
    }

    for (int jt = 0; jt < 64; ++jt) {
        const int stg = jt % 3;

        uint64_t u0 = (*(const uint64_t*)(g_mask + mrow0 + 2 * jt)) >> (2 * ci);
        uint64_t u1 = (*(const uint64_t*)(g_mask + mrow1 + 2 * jt)) >> (2 * ci);

        if (jt < 62) {
            const int j2 = (jt + 2) * 64;
            const int ns = (jt + 2) % 3;
            __nv_bfloat16* sKs = sK + ns * 64 * 72;
            __nv_bfloat16* sVs = sV + ns * 64 * 72;
#pragma unroll
            for (int p = 0; p < 2; ++p) {
                const int r = lr + p * 32;
                cp16(&sKs[r * 72 + lc8], g_K + (size_t)(j2 + r) * FF + hc + lc8);
                cp16(&sVs[r * 72 + lc8], g_V + (size_t)(j2 + r) * FF + hc + lc8);
            }
            cp_commit();
            cp_wait<2>();
        } else if (jt == 62) {
            cp_wait<1>();
        } else {
            cp_wait<0>();
        }
        __syncthreads();

        const __nv_bfloat16* sKc = sK + stg * 64 * 72;
        const __nv_bfloat16* sVc = sV + stg * 64 * 72;

        // S = Q K^T (base-2 scaled via Q)
        float s[8][4];
#pragma unroll
        for (int t = 0; t < 8; ++t)
#pragma unroll
            for (int i = 0; i < 4; ++i) s[t][i] = 0.f;

#pragma unroll
        for (int ks = 0; ks < 4; ++ks) {
#pragma unroll
            for (int g = 0; g < 4; ++g) {
                const int row = g * 16 + (lane & 7) + (lane >> 4) * 8;
                const int col = ks * 16 + ((lane >> 3) & 1) * 8;
                uint32_t b0, b1, b2, b3;
                ldsm_x4(smem_u32(&sKc[row * 72 + col]), b0, b1, b2, b3);
                mma16816(s[2 * g],     qf[ks], b0, b1);
                mma16816(s[2 * g + 1], qf[ks], b2, b3);
            }
        }

        // p = bit ? exp2(s) : 0 ; accumulate per-lane l
#pragma unroll
        for (int t = 0; t < 8; ++t) {
            float p00 = ex2(s[t][0]);
            float p01 = ex2(s[t][1]);
            float p10 = ex2(s[t][2]);
            float p11 = ex2(s[t][3]);
            p00 = ((u0 >> (8 * t)) & 1)     ? p00 : 0.f;
            p01 = ((u0 >> (8 * t + 1)) & 1) ? p01 : 0.f;
            p10 = ((u1 >> (8 * t)) & 1)     ? p10 : 0.f;
            p11 = ((u1 >> (8 * t + 1)) & 1) ? p11 : 0.f;
            l0 += p00 + p01;
            l1 += p10 + p11;
            s[t][0] = p00; s[t][1] = p01; s[t][2] = p10; s[t][3] = p11;
        }

        // O += P @ V
#pragma unroll
        for (int kg = 0; kg < 4; ++kg) {
            uint32_t pa[4];
            pa[0] = packbf(s[2 * kg][0],     s[2 * kg][1]);
            pa[1] = packbf(s[2 * kg][2],     s[2 * kg][3]);
            pa[2] = packbf(s[2 * kg + 1][0], s[2 * kg + 1][1]);
            pa[3] = packbf(s[2 * kg + 1][2], s[2 * kg + 1][3]);
#pragma unroll
            for (int dg = 0; dg < 4; ++dg) {
                const int row = kg * 16 + (lane & 7) + ((lane >> 3) & 1) * 8;
                const int col = dg * 16 + (lane >> 4) * 8;
                uint32_t b0, b1, b2, b3;
                ldsm_x4_t(smem_u32(&sVc[row * 72 + col]), b0, b1, b2, b3);
                mma16816(O[2 * dg],     pa, b0, b1);
                mma16816(O[2 * dg + 1], pa, b2, b3);
            }
        }
        __syncthreads();
    }

    // reduce l over the quad, then epilogue: normalize, residual, ELU
    l0 += __shfl_xor_sync(0xffffffffu, l0, 1);
    l0 += __shfl_xor_sync(0xffffffffu, l0, 2);
    l1 += __shfl_xor_sync(0xffffffffu, l1, 1);
    l1 += __shfl_xor_sync(0xffffffffu, l1, 2);
    const float inv0 = 1.f / l0;
    const float inv1 = 1.f / l1;
    const int r0 = r0g;
    const int r1 = r0 + 8;
#pragma unroll
    for (int t = 0; t < 8; ++t) {
        const int col = hc + t * 8 + ci * 2;
        float2 x0 = *(const float2*)(x + (size_t)r0 * FF + col);
        float2 x1 = *(const float2*)(x + (size_t)r1 * FF + col);
        float v00 = O[t][0] * inv0 + x0.x;
        float v01 = O[t][1] * inv0 + x0.y;
        float v10 = O[t][2] * inv1 + x1.x;
        float v11 = O[t][3] * inv1 + x1.y;
        v00 = (v00 > 0.f) ? v00 : expm1f(v00);
        v01 = (v01 > 0.f) ? v01 : expm1f(v01);
        v10 = (v10 > 0.f) ? v10 : expm1f(v10);
        v11 = (v11 > 0.f) ? v11 : expm1f(v11);
        *(float2*)(out + (size_t)r0 * FF + col) = make_float2(v00, v01);
        *(float2*)(out + (size_t)r1 * FF + col) = make_float2(v10, v11);
    }
}

extern "C" void kernel_launch(void* const* d_in, const int* in_sizes, int n_in,
                              void* d_out, int out_size) {
    const float* x  = (const float*)d_in[0];
    const float* Wq = (const float*)d_in[1];
    const float* Wk = (const float*)d_in[2];
    const float* Wv = (const float*)d_in[3];
    const int* adj  = (const int*)d_in[4];
    float* out = (float*)d_out;

    // One-time setup on the first (correctness, non-captured) call.
    static cudaStream_t s2 = nullptr;
    static cudaEvent_t evFork = nullptr, evJoin = nullptr;
    if (s2 == nullptr) {
        int prLow = 0, prHigh = 0;
        cudaDeviceGetStreamPriorityRange(&prLow, &prHigh);  // prLow = lowest priority
        cudaStreamCreateWithPriority(&s2, cudaStreamNonBlocking, prLow);
        cudaEventCreateWithFlags(&evFork, cudaEventDisableTiming);
        cudaEventCreateWithFlags(&evJoin, cudaEventDisableTiming);
        cudaFuncSetAttribute(attn_kernel, cudaFuncAttributeMaxDynamicSharedMemorySize, ATTN_SMEM);
    }

    // proj FIRST on the capture stream: its CTAs get placed immediately.
    proj_kernel<<<dim3(32, 12), 256>>>(x, Wq, Wk, Wv);
    // pack on the low-priority stream backfills remaining SM slots.
    cudaEventRecord(evFork, 0);
    cudaStreamWaitEvent(s2, evFork, 0);
    pack_kernel<<<2048, 256, 0, s2>>>(adj);
    // Join: attn needs both the bitmask and Q/K/V.
    cudaEventRecord(evJoin, s2);
    cudaStreamWaitEvent(0, evJoin, 0);
    attn_kernel<<<dim3(32, 8), 256, ATTN_SMEM>>>(x, out);
}

// round 9
// speedup vs baseline: 1.0923x; 1.0923x over previous
#include <cuda_runtime.h>
#include <cuda_bf16.h>
#include <cstdint>

// ---------------------------------------------------------------------------
// GraphAttentionLayer: N=4096, F=512, H=8, d=64
//  1) cvt_kernel:  x, Wq, Wk, Wv f32 -> bf16 device globals (pure stream)
//  2) proj_kernel: Q/K/V = xb @ Wb^T, bf16 cp.async 2-stage GEMM
//  3) pack_kernel: adj -> bitmask (16 MB), 32-reg grid-stride, ~6.5 TB/s
//  4) attn_kernel: flash attention, bitmask mask, 4-stage cp.async ring with
//     ONE __syncthreads per tile, fixed-max base-2 softmax.
// Sequential default-stream launches (stream overlap proven useless R7/R8).
// ---------------------------------------------------------------------------

#define NN 4096
#define FF 512
#define NH 8
#define HD 64

__device__ __nv_bfloat16 g_Q[NN * FF];
__device__ __nv_bfloat16 g_K[NN * FF];
__device__ __nv_bfloat16 g_V[NN * FF];
__device__ __nv_bfloat16 g_xb[NN * FF];
__device__ __nv_bfloat16 g_Wb[3 * FF * FF];
__device__ uint32_t g_mask[NH * NN * (NN / 32)];   // 16 MB

__device__ __forceinline__ uint32_t smem_u32(const void* p) {
    return (uint32_t)__cvta_generic_to_shared(p);
}

__device__ __forceinline__ void ldsm_x4(uint32_t addr, uint32_t& r0, uint32_t& r1,
                                        uint32_t& r2, uint32_t& r3) {
    asm volatile("ldmatrix.sync.aligned.m8n8.x4.shared.b16 {%0,%1,%2,%3}, [%4];"
                 : "=r"(r0), "=r"(r1), "=r"(r2), "=r"(r3) : "r"(addr));
}

__device__ __forceinline__ void ldsm_x4_t(uint32_t addr, uint32_t& r0, uint32_t& r1,
                                          uint32_t& r2, uint32_t& r3) {
    asm volatile("ldmatrix.sync.aligned.m8n8.x4.trans.shared.b16 {%0,%1,%2,%3}, [%4];"
                 : "=r"(r0), "=r"(r1), "=r"(r2), "=r"(r3) : "r"(addr));
}

__device__ __forceinline__ void mma16816(float* d, const uint32_t* a, uint32_t b0, uint32_t b1) {
    asm volatile("mma.sync.aligned.m16n8k16.row.col.f32.bf16.bf16.f32 "
                 "{%0,%1,%2,%3}, {%4,%5,%6,%7}, {%8,%9}, {%0,%1,%2,%3};"
                 : "+f"(d[0]), "+f"(d[1]), "+f"(d[2]), "+f"(d[3])
                 : "r"(a[0]), "r"(a[1]), "r"(a[2]), "r"(a[3]), "r"(b0), "r"(b1));
}

__device__ __forceinline__ uint32_t packbf(float lo, float hi) {
    uint32_t r;
    asm("cvt.rn.bf16x2.f32 %0, %1, %2;" : "=r"(r) : "f"(hi), "f"(lo));
    return r;
}

__device__ __forceinline__ float ex2(float x) {
    float r;
    asm("ex2.approx.ftz.f32 %0, %1;" : "=f"(r) : "f"(x));
    return r;
}

__device__ __forceinline__ void cp16(void* s, const void* g) {
    asm volatile("cp.async.cg.shared.global [%0], [%1], 16;"
                 :: "r"(smem_u32(s)), "l"(g));
}
__device__ __forceinline__ void cp_commit() { asm volatile("cp.async.commit_group;"); }
template <int n>
__device__ __forceinline__ void cp_wait() { asm volatile("cp.async.wait_group %0;" :: "n"(n)); }

// ---------------------------------------------------------------------------
// cvt: f32 -> bf16 for x (2M elts) and Wq/Wk/Wv (256K each). One float4/thread.
// ---------------------------------------------------------------------------
#define XN4 (NN * FF / 4)        // 524288
#define WN4 (FF * FF / 4)        // 65536
#define CVT_TOTAL (XN4 + 3 * WN4)   // 720896 = 2816 * 256

__global__ __launch_bounds__(256) void cvt_kernel(const float* __restrict__ x,
                                                  const float* __restrict__ Wq,
                                                  const float* __restrict__ Wk,
                                                  const float* __restrict__ Wv) {
    const int i = blockIdx.x * 256 + threadIdx.x;
    if (i >= CVT_TOTAL) return;
    const float* src;
    __nv_bfloat16* dst;
    int off;
    if (i < XN4) {
        src = x; dst = g_xb; off = i;
    } else {
        const int j = i - XN4;
        const int m = j / WN4;
        off = j - m * WN4;
        src = (m == 0) ? Wq : (m == 1) ? Wk : Wv;
        dst = g_Wb + m * (FF * FF);
    }
    float4 v = __ldg((const float4*)src + off);
    uint2 st;
    st.x = packbf(v.x, v.y);
    st.y = packbf(v.z, v.w);
    *((uint2*)dst + off) = st;
}

// ---------------------------------------------------------------------------
// Pack adj -> bitmask. 32 regs, grid-stride, ~6.5 TB/s.
// ---------------------------------------------------------------------------
__global__ __launch_bounds__(256) void pack_kernel(const int* __restrict__ adj) {
    const int lane = threadIdx.x & 31;
    const int wg = (blockIdx.x * blockDim.x + threadIdx.x) >> 5;
    const int nw = (gridDim.x * blockDim.x) >> 5;
    const int grp = lane >> 3;
    const int shift = (lane & 7) * 4;
    const int total = NH * NN * (NN / 128);   // 1048576 tiles

    for (int T = wg * 2; T < total; T += nw * 2) {
#pragma unroll
        for (int u = 0; u < 2; ++u) {
            const int t = T + u;
            int4 v = __ldg((const int4*)(adj + (size_t)t * 128) + lane);
            uint32_t w = ((uint32_t)(v.x > 0) | ((uint32_t)(v.y > 0) << 1) |
                          ((uint32_t)(v.z > 0) << 2) | ((uint32_t)(v.w > 0) << 3)) << shift;
            w |= __shfl_xor_sync(0xffffffffu, w, 1);
            w |= __shfl_xor_sync(0xffffffffu, w, 2);
            w |= __shfl_xor_sync(0xffffffffu, w, 4);
            if ((lane & 7) == 0) g_mask[(size_t)t * 4 + grp] = w;
        }
    }
}

// ---------------------------------------------------------------------------
// Projection GEMM (bf16 inputs): C[i,j] = sum_k xb[i,k] * Wb[j,k].
// Tile 128x128x64, cp.async 2-stage, 256 threads (8 warps 4x2), grid (32,12).
// Dynamic smem 73728 B: sA[2][128][72], sB[2][128][72].
// ---------------------------------------------------------------------------
#define PJ_ST (128 * 72)
#define PROJ_SMEM (4 * PJ_ST * 2)

__global__ __launch_bounds__(256) void proj_kernel() {
    extern __shared__ __nv_bfloat16 ps[];
    __nv_bfloat16* sA = ps;                    // [2][128][72]
    __nv_bfloat16* sB = ps + 2 * PJ_ST;        // [2][128][72]

    const int tid = threadIdx.x;
    const int lane = tid & 31;
    const int warp = tid >> 5;
    const int wr = warp & 3;
    const int wc = warp >> 2;
    const int mblk = blockIdx.x;
    const int mat = blockIdx.y >> 2;
    const int nblk = blockIdx.y & 3;

    const __nv_bfloat16* Ab = g_xb + (size_t)(mblk * 128) * FF;
    const __nv_bfloat16* Bb = g_Wb + (size_t)mat * FF * FF + (size_t)(nblk * 128) * FF;
    __nv_bfloat16* dst = (mat == 0) ? g_Q : (mat == 1) ? g_K : g_V;
    // Q scale = 1/sqrt(512) * log2(e)   (softmax in base-2)
    const float scale = (mat == 0) ? (0.044194173824159216f * 1.4426950408889634f) : 1.0f;

    float acc[2][8][4];
#pragma unroll
    for (int mt = 0; mt < 2; ++mt)
#pragma unroll
        for (int t = 0; t < 8; ++t)
#pragma unroll
            for (int i = 0; i < 4; ++i) acc[mt][t][i] = 0.f;

    const int lr = tid >> 3;           // 0..31
    const int lc8 = (tid & 7) * 8;     // 0..56

    // async-load k-tile kt into stage st
    auto load_tile = [&](int st, int kt) {
        const int k0 = kt * 64;
#pragma unroll
        for (int p = 0; p < 4; ++p) {
            const int r = lr + p * 32;
            cp16(&sA[st * PJ_ST + r * 72 + lc8], Ab + (size_t)r * FF + k0 + lc8);
            cp16(&sB[st * PJ_ST + r * 72 + lc8], Bb + (size_t)r * FF + k0 + lc8);
        }
        cp_commit();
    };

    load_tile(0, 0);

    for (int kt = 0; kt < 8; ++kt) {
        const int cur = kt & 1;
        if (kt < 7) {
            load_tile(cur ^ 1, kt + 1);
            cp_wait<1>();
        } else {
            cp_wait<0>();
        }
        __syncthreads();

        const __nv_bfloat16* sAc = sA + cur * PJ_ST;
        const __nv_bfloat16* sBc = sB + cur * PJ_ST;
#pragma unroll
        for (int ks = 0; ks < 4; ++ks) {
            uint32_t af[2][4];
#pragma unroll
            for (int mt = 0; mt < 2; ++mt) {
                const int row = wr * 32 + mt * 16 + (lane & 7) + ((lane >> 3) & 1) * 8;
                const int col = ks * 16 + (lane >> 4) * 8;
                ldsm_x4(smem_u32(&sAc[row * 72 + col]), af[mt][0], af[mt][1], af[mt][2], af[mt][3]);
            }
#pragma unroll
            for (int g = 0; g < 4; ++g) {
                const int row = wc * 64 + g * 16 + (lane & 7) + (lane >> 4) * 8;
                const int col = ks * 16 + ((lane >> 3) & 1) * 8;
                uint32_t b0, b1, b2, b3;
                ldsm_x4(smem_u32(&sBc[row * 72 + col]), b0, b1, b2, b3);
#pragma unroll
                for (int mt = 0; mt < 2; ++mt) {
                    mma16816(acc[mt][2 * g],     af[mt], b0, b1);
                    mma16816(acc[mt][2 * g + 1], af[mt], b2, b3);
                }
            }
        }
        __syncthreads();
    }

#pragma unroll
    for (int mt = 0; mt < 2; ++mt) {
        const int row = mblk * 128 + wr * 32 + mt * 16 + (lane >> 2);
#pragma unroll
        for (int t = 0; t < 8; ++t) {
            const int col = nblk * 128 + wc * 64 + t * 8 + (lane & 3) * 2;
            *(uint32_t*)&dst[(size_t)row * FF + col] =
                packbf(acc[mt][t][0] * scale, acc[mt][t][1] * scale);
            *(uint32_t*)&dst[(size_t)(row + 8) * FF + col] =
                packbf(acc[mt][t][2] * scale, acc[mt][t][3] * scale);
        }
    }
}

// ---------------------------------------------------------------------------
// Flash attention: bitmask masking, 4-stage cp.async ring, ONE sync per tile,
// fixed-max base-2 softmax. grid=(32,8), 256 threads, 2 CTAs/SM.
// Dynamic smem 73728 B: sK[4][64][72] bf16, sV[4][64][72] bf16.
// Single-sync safety: at tile jt the prefetch writes stage (jt+2)&3; every
// warp has passed SYNC_{jt-1}, hence finished compute jt-2 = last reader of
// that stage. Exactly 4 stages required.
// ---------------------------------------------------------------------------
#define ST_BYTES (64 * 72 * 2)
#define ATTN_SMEM (8 * ST_BYTES)

__global__ __launch_bounds__(256, 2) void attn_kernel(const float* __restrict__ x,
                                                      float* __restrict__ out) {
    extern __shared__ char sm[];
    __nv_bfloat16* sK = (__nv_bfloat16*)sm;                      // [4][64][72]
    __nv_bfloat16* sV = (__nv_bfloat16*)(sm + 4 * ST_BYTES);     // [4][64][72]

    const int tid = threadIdx.x;
    const int lane = tid & 31;
    const int warp = tid >> 5;
    const int q0 = blockIdx.x * 128;
    const int h = blockIdx.y;
    const int hc = h * HD;

    const int lr = tid >> 3;           // 0..31
    const int lc8 = (tid & 7) * 8;     // 0..56

    // --- stage Q (128 x 64, stride 72) through sK rows 0..127, grab frags ---
#pragma unroll
    for (int p = 0; p < 4; ++p) {
        const int r = lr + p * 32;
        uint4 v = *(const uint4*)(g_Q + (size_t)(q0 + r) * FF + hc + lc8);
        *(uint4*)&sK[r * 72 + lc8] = v;
    }
    __syncthreads();

    const int rw = warp * 16;
    uint32_t qf[4][4];
#pragma unroll
    for (int ks = 0; ks < 4; ++ks) {
        const int row = rw + (lane & 7) + ((lane >> 3) & 1) * 8;
        const int col = ks * 16 + (lane >> 4) * 8;
        ldsm_x4(smem_u32(&sK[row * 72 + col]), qf[ks][0], qf[ks][1], qf[ks][2], qf[ks][3]);
    }
    __syncthreads();   // Q frags extracted; stages 0..1 may be overwritten

    float O[8][4];
#pragma unroll
    for (int t = 0; t < 8; ++t)
#pragma unroll
        for (int i = 0; i < 4; ++i) O[t][i] = 0.f;

    float l0 = 0.f, l1 = 0.f;          // per-lane partial sums (no running max)

    const int ci = lane & 3;
    const int rl0 = rw + (lane >> 2);
    const int r0g = q0 + rl0;
    const size_t mrow0 = ((size_t)h * NN + r0g) * (NN / 32);
    const size_t mrow1 = mrow0 + 8 * (NN / 32);

    // prologue: async-load tiles 0 and 1 into stages 0, 1 (one group each)
#pragma unroll
    for (int pre = 0; pre < 2; ++pre) {
        __nv_bfloat16* sKs = sK + pre * 64 * 72;
        __nv_bfloat16* sVs = sV + pre * 64 * 72;
#pragma unroll
        for (int p = 0; p < 2; ++p) {
            const int r = lr + p * 32;
            cp16(&sKs[r * 72 + lc8], g_K + (size_t)(pre * 64 + r) * FF + hc + lc8);
            cp16(&sVs[r * 72 + lc8], g_V + (size_t)(pre * 64 + r) * FF + hc + lc8);
        }
        cp_commit();
    }

    for (int jt = 0; jt < 64; ++jt) {
        const int stg = jt & 3;

        uint64_t u0 = (*(const uint64_t*)(g_mask + mrow0 + 2 * jt)) >> (2 * ci);
        uint64_t u1 = (*(const uint64_t*)(g_mask + mrow1 + 2 * jt)) >> (2 * ci);

        if (jt < 62) {
            const int j2 = (jt + 2) * 64;
            const int ns = (jt + 2) & 3;
            __nv_bfloat16* sKs = sK + ns * 64 * 72;
            __nv_bfloat16* sVs = sV + ns * 64 * 72;
#pragma unroll
            for (int p = 0; p < 2; ++p) {
                const int r = lr + p * 32;
                cp16(&sKs[r * 72 + lc8], g_K + (size_t)(j2 + r) * FF + hc + lc8);
                cp16(&sVs[r * 72 + lc8], g_V + (size_t)(j2 + r) * FF + hc + lc8);
            }
            cp_commit();
            cp_wait<2>();
        } else if (jt == 62) {
            cp_wait<1>();
        } else {
            cp_wait<0>();
        }
        __syncthreads();   // the ONLY barrier in the tile

        const __nv_bfloat16* sKc = sK + stg * 64 * 72;
        const __nv_bfloat16* sVc = sV + stg * 64 * 72;

        // S = Q K^T (base-2 scaled via Q)
        float s[8][4];
#pragma unroll
        for (int t = 0; t < 8; ++t)
#pragma unroll
            for (int i = 0; i < 4; ++i) s[t][i] = 0.f;

#pragma unroll
        for (int ks = 0; ks < 4; ++ks) {
#pragma unroll
            for (int g = 0; g < 4; ++g) {
                const int row = g * 16 + (lane & 7) + (lane >> 4) * 8;
                const int col = ks * 16 + ((lane >> 3) & 1) * 8;
                uint32_t b0, b1, b2, b3;
                ldsm_x4(smem_u32(&sKc[row * 72 + col]), b0, b1, b2, b3);
                mma16816(s[2 * g],     qf[ks], b0, b1);
                mma16816(s[2 * g + 1], qf[ks], b2, b3);
            }
        }

        // p = bit ? exp2(s) : 0 ; accumulate per-lane l
#pragma unroll
        for (int t = 0; t < 8; ++t) {
            float p00 = ex2(s[t][0]);
            float p01 = ex2(s[t][1]);
            float p10 = ex2(s[t][2]);
            float p11 = ex2(s[t][3]);
            p00 = ((u0 >> (8 * t)) & 1)     ? p00 : 0.f;
            p01 = ((u0 >> (8 * t + 1)) & 1) ? p01 : 0.f;
            p10 = ((u1 >> (8 * t)) & 1)     ? p10 : 0.f;
            p11 = ((u1 >> (8 * t + 1)) & 1) ? p11 : 0.f;
            l0 += p00 + p01;
            l1 += p10 + p11;
            s[t][0] = p00; s[t][1] = p01; s[t][2] = p10; s[t][3] = p11;
        }

        // O += P @ V
#pragma unroll
        for (int kg = 0; kg < 4; ++kg) {
            uint32_t pa[4];
            pa[0] = packbf(s[2 * kg][0],     s[2 * kg][1]);
            pa[1] = packbf(s[2 * kg][2],     s[2 * kg][3]);
            pa[2] = packbf(s[2 * kg + 1][0], s[2 * kg + 1][1]);
            pa[3] = packbf(s[2 * kg + 1][2], s[2 * kg + 1][3]);
#pragma unroll
            for (int dg = 0; dg < 4; ++dg) {
                const int row = kg * 16 + (lane & 7) + ((lane >> 3) & 1) * 8;
                const int col = dg * 16 + (lane >> 4) * 8;
                uint32_t b0, b1, b2, b3;
                ldsm_x4_t(smem_u32(&sVc[row * 72 + col]), b0, b1, b2, b3);
                mma16816(O[2 * dg],     pa, b0, b1);
                mma16816(O[2 * dg + 1], pa, b2, b3);
            }
        }
        // no trailing barrier: 4-stage ring makes it unnecessary
    }

    // reduce l over the quad, then epilogue: normalize, residual, ELU
    l0 += __shfl_xor_sync(0xffffffffu, l0, 1);
    l0 += __shfl_xor_sync(0xffffffffu, l0, 2);
    l1 += __shfl_xor_sync(0xffffffffu, l1, 1);
    l1 += __shfl_xor_sync(0xffffffffu, l1, 2);
    const float inv0 = 1.f / l0;
    const float inv1 = 1.f / l1;
    const int r0 = r0g;
    const int r1 = r0 + 8;
#pragma unroll
    for (int t = 0; t < 8; ++t) {
        const int col = hc + t * 8 + ci * 2;
        float2 x0 = *(const float2*)(x + (size_t)r0 * FF + col);
        float2 x1 = *(const float2*)(x + (size_t)r1 * FF + col);
        float v00 = O[t][0] * inv0 + x0.x;
        float v01 = O[t][1] * inv0 + x0.y;
        float v10 = O[t][2] * inv1 + x1.x;
        float v11 = O[t][3] * inv1 + x1.y;
        v00 = (v00 > 0.f) ? v00 : expm1f(v00);
        v01 = (v01 > 0.f) ? v01 : expm1f(v01);
        v10 = (v10 > 0.f) ? v10 : expm1f(v10);
        v11 = (v11 > 0.f) ? v11 : expm1f(v11);
        *(float2*)(out + (size_t)r0 * FF + col) = make_float2(v00, v01);
        *(float2*)(out + (size_t)r1 * FF + col) = make_float2(v10, v11);
    }
}

extern "C" void kernel_launch(void* const* d_in, const int* in_sizes, int n_in,
                              void* d_out, int out_size) {
    const float* x  = (const float*)d_in[0];
    const float* Wq = (const float*)d_in[1];
    const float* Wk = (const float*)d_in[2];
    const float* Wv = (const float*)d_in[3];
    const int* adj  = (const int*)d_in[4];
    float* out = (float*)d_out;

    cudaFuncSetAttribute(proj_kernel, cudaFuncAttributeMaxDynamicSharedMemorySize, PROJ_SMEM);
    cudaFuncSetAttribute(attn_kernel, cudaFuncAttributeMaxDynamicSharedMemorySize, ATTN_SMEM);

    cvt_kernel<<<2816, 256>>>(x, Wq, Wk, Wv);
    proj_kernel<<<dim3(32, 12), 256, PROJ_SMEM>>>();
    pack_kernel<<<2048, 256>>>(adj);
    attn_kernel<<<dim3(32, 8), 256, ATTN_SMEM>>>(x, out);
}

// round 11
// speedup vs baseline: 1.2468x; 1.1414x over previous
#include <cuda_runtime.h>
#include <cuda_bf16.h>
#include <cstdint>

// ---------------------------------------------------------------------------
// GraphAttentionLayer: N=4096, F=512, H=8, d=64
//  1) cvt_kernel:  x, Wq/Wk/Wv f32 -> bf16 globals
//  2) proj_kernel: Q/K/V bf16 GEMM (cp.async 2-stage)
//  3) attn_kernel: flash attention with the RAW adj stream fused in-loop as
//     registered LDG.64s (split per n-half for register budget), 4-stage
//     cp.async K/V ring, one __syncthreads per tile, fixed-max base-2 softmax.
// No pack pass: the 512 MB adj read overlaps the tensor-bound mainloop.
// ---------------------------------------------------------------------------

#define NN 4096
#define FF 512
#define NH 8
#define HD 64

__device__ __nv_bfloat16 g_Q[NN * FF];
__device__ __nv_bfloat16 g_K[NN * FF];
__device__ __nv_bfloat16 g_V[NN * FF];
__device__ __nv_bfloat16 g_xb[NN * FF];
__device__ __nv_bfloat16 g_Wb[3 * FF * FF];

__device__ __forceinline__ uint32_t smem_u32(const void* p) {
    return (uint32_t)__cvta_generic_to_shared(p);
}
__device__ __forceinline__ void ldsm_x4(uint32_t addr, uint32_t& r0, uint32_t& r1,
                                        uint32_t& r2, uint32_t& r3) {
    asm volatile("ldmatrix.sync.aligned.m8n8.x4.shared.b16 {%0,%1,%2,%3}, [%4];"
                 : "=r"(r0), "=r"(r1), "=r"(r2), "=r"(r3) : "r"(addr));
}
__device__ __forceinline__ void ldsm_x4_t(uint32_t addr, uint32_t& r0, uint32_t& r1,
                                          uint32_t& r2, uint32_t& r3) {
    asm volatile("ldmatrix.sync.aligned.m8n8.x4.trans.shared.b16 {%0,%1,%2,%3}, [%4];"
                 : "=r"(r0), "=r"(r1), "=r"(r2), "=r"(r3) : "r"(addr));
}
__device__ __forceinline__ void mma16816(float* d, const uint32_t* a, uint32_t b0, uint32_t b1) {
    asm volatile("mma.sync.aligned.m16n8k16.row.col.f32.bf16.bf16.f32 "
                 "{%0,%1,%2,%3}, {%4,%5,%6,%7}, {%8,%9}, {%0,%1,%2,%3};"
                 : "+f"(d[0]), "+f"(d[1]), "+f"(d[2]), "+f"(d[3])
                 : "r"(a[0]), "r"(a[1]), "r"(a[2]), "r"(a[3]), "r"(b0), "r"(b1));
}
__device__ __forceinline__ uint32_t packbf(float lo, float hi) {
    uint32_t r;
    asm("cvt.rn.bf16x2.f32 %0, %1, %2;" : "=r"(r) : "f"(hi), "f"(lo));
    return r;
}
__device__ __forceinline__ float ex2(float x) {
    float r;
    asm("ex2.approx.ftz.f32 %0, %1;" : "=f"(r) : "f"(x));
    return r;
}
__device__ __forceinline__ void cp16(void* s, const void* g) {
    asm volatile("cp.async.cg.shared.global [%0], [%1], 16;"
                 :: "r"(smem_u32(s)), "l"(g));
}
__device__ __forceinline__ void cp_commit() { asm volatile("cp.async.commit_group;"); }
template <int n>
__device__ __forceinline__ void cp_wait() { asm volatile("cp.async.wait_group %0;" :: "n"(n)); }

// ---------------------------------------------------------------------------
// cvt: f32 -> bf16 for x and Wq/Wk/Wv.
// ---------------------------------------------------------------------------
#define XN4 (NN * FF / 4)
#define WN4 (FF * FF / 4)
#define CVT_TOTAL (XN4 + 3 * WN4)

__global__ __launch_bounds__(256) void cvt_kernel(const float* __restrict__ x,
                                                  const float* __restrict__ Wq,
                                                  const float* __restrict__ Wk,
                                                  const float* __restrict__ Wv) {
    const int i = blockIdx.x * 256 + threadIdx.x;
    if (i >= CVT_TOTAL) return;
    const float* src;
    __nv_bfloat16* dst;
    int off;
    if (i < XN4) {
        src = x; dst = g_xb; off = i;
    } else {
        const int j = i - XN4;
        const int m = j / WN4;
        off = j - m * WN4;
        src = (m == 0) ? Wq : (m == 1) ? Wk : Wv;
        dst = g_Wb + m * (FF * FF);
    }
    float4 v = __ldg((const float4*)src + off);
    uint2 st;
    st.x = packbf(v.x, v.y);
    st.y = packbf(v.z, v.w);
    *((uint2*)dst + off) = st;
}

// ---------------------------------------------------------------------------
// Projection GEMM (bf16): tile 128x128x64, cp.async 2-stage. grid (32,12).
// ---------------------------------------------------------------------------
#define PJ_ST (128 * 72)
#define PROJ_SMEM (4 * PJ_ST * 2)

__global__ __launch_bounds__(256) void proj_kernel() {
    extern __shared__ __nv_bfloat16 ps[];
    __nv_bfloat16* sA = ps;
    __nv_bfloat16* sB = ps + 2 * PJ_ST;

    const int tid = threadIdx.x;
    const int lane = tid & 31;
    const int warp = tid >> 5;
    const int wr = warp & 3;
    const int wc = warp >> 2;
    const int mblk = blockIdx.x;
    const int mat = blockIdx.y >> 2;
    const int nblk = blockIdx.y & 3;

    const __nv_bfloat16* Ab = g_xb + (size_t)(mblk * 128) * FF;
    const __nv_bfloat16* Bb = g_Wb + (size_t)mat * FF * FF + (size_t)(nblk * 128) * FF;
    __nv_bfloat16* dst = (mat == 0) ? g_Q : (mat == 1) ? g_K : g_V;
    // Q scale = 1/sqrt(512) * log2(e)   (softmax in base-2)
    const float scale = (mat == 0) ? (0.044194173824159216f * 1.4426950408889634f) : 1.0f;

    float acc[2][8][4];
#pragma unroll
    for (int mt = 0; mt < 2; ++mt)
#pragma unroll
        for (int t = 0; t < 8; ++t)
#pragma unroll
            for (int i = 0; i < 4; ++i) acc[mt][t][i] = 0.f;

    const int lr = tid >> 3;
    const int lc8 = (tid & 7) * 8;

    auto load_tile = [&](int st, int kt) {
        const int k0 = kt * 64;
#pragma unroll
        for (int p = 0; p < 4; ++p) {
            const int r = lr + p * 32;
            cp16(&sA[st * PJ_ST + r * 72 + lc8], Ab + (size_t)r * FF + k0 + lc8);
            cp16(&sB[st * PJ_ST + r * 72 + lc8], Bb + (size_t)r * FF + k0 + lc8);
        }
        cp_commit();
    };

    load_tile(0, 0);

    for (int kt = 0; kt < 8; ++kt) {
        const int cur = kt & 1;
        if (kt < 7) {
            load_tile(cur ^ 1, kt + 1);
            cp_wait<1>();
        } else {
            cp_wait<0>();
        }
        __syncthreads();

        const __nv_bfloat16* sAc = sA + cur * PJ_ST;
        const __nv_bfloat16* sBc = sB + cur * PJ_ST;
#pragma unroll
        for (int ks = 0; ks < 4; ++ks) {
            uint32_t af[2][4];
#pragma unroll
            for (int mt = 0; mt < 2; ++mt) {
                const int row = wr * 32 + mt * 16 + (lane & 7) + ((lane >> 3) & 1) * 8;
                const int col = ks * 16 + (lane >> 4) * 8;
                ldsm_x4(smem_u32(&sAc[row * 72 + col]), af[mt][0], af[mt][1], af[mt][2], af[mt][3]);
            }
#pragma unroll
            for (int g = 0; g < 4; ++g) {
                const int row = wc * 64 + g * 16 + (lane & 7) + (lane >> 4) * 8;
                const int col = ks * 16 + ((lane >> 3) & 1) * 8;
                uint32_t b0, b1, b2, b3;
                ldsm_x4(smem_u32(&sBc[row * 72 + col]), b0, b1, b2, b3);
#pragma unroll
                for (int mt = 0; mt < 2; ++mt) {
                    mma16816(acc[mt][2 * g],     af[mt], b0, b1);
                    mma16816(acc[mt][2 * g + 1], af[mt], b2, b3);
                }
            }
        }
        __syncthreads();
    }

#pragma unroll
    for (int mt = 0; mt < 2; ++mt) {
        const int row = mblk * 128 + wr * 32 + mt * 16 + (lane >> 2);
#pragma unroll
        for (int t = 0; t < 8; ++t) {
            const int col = nblk * 128 + wc * 64 + t * 8 + (lane & 3) * 2;
            *(uint32_t*)&dst[(size_t)row * FF + col] =
                packbf(acc[mt][t][0] * scale, acc[mt][t][1] * scale);
            *(uint32_t*)&dst[(size_t)(row + 8) * FF + col] =
                packbf(acc[mt][t][2] * scale, acc[mt][t][3] * scale);
        }
    }
}

// ---------------------------------------------------------------------------
// Fused flash attention: raw adj via in-loop LDG.64 (no pack pass), 4-stage
// cp.async K/V ring, ONE sync per tile, fixed-max base-2 softmax.
// grid=(32,8), 256 threads (8 warps x 16 q rows), 2 CTAs/SM.
// S-mma is split into two n-halves so only 16 adj regs are live at a time.
// ---------------------------------------------------------------------------
#define ST_BYTES (64 * 72 * 2)
#define ATTN_SMEM (8 * ST_BYTES)

__global__ __launch_bounds__(256, 2) void attn_kernel(const float* __restrict__ x,
                                                      const int* __restrict__ adj,
                                                      float* __restrict__ out) {
    extern __shared__ char sm[];
    __nv_bfloat16* sK = (__nv_bfloat16*)sm;                      // [4][64][72]
    __nv_bfloat16* sV = (__nv_bfloat16*)(sm + 4 * ST_BYTES);     // [4][64][72]

    const int tid = threadIdx.x;
    const int lane = tid & 31;
    const int warp = tid >> 5;
    const int q0 = blockIdx.x * 128;
    const int h = blockIdx.y;
    const int hc = h * HD;

    const int lr = tid >> 3;           // 0..31
    const int lc8 = (tid & 7) * 8;     // 0..56

    // --- stage Q (128 x 64, stride 72) through sK rows, grab frags ---
#pragma unroll
    for (int p = 0; p < 4; ++p) {
        const int r = lr + p * 32;
        uint4 v = *(const uint4*)(g_Q + (size_t)(q0 + r) * FF + hc + lc8);
        *(uint4*)&sK[r * 72 + lc8] = v;
    }
    __syncthreads();

    const int rw = warp * 16;
    uint32_t qf[4][4];
#pragma unroll
    for (int ks = 0; ks < 4; ++ks) {
        const int row = rw + (lane & 7) + ((lane >> 3) & 1) * 8;
        const int col = ks * 16 + (lane >> 4) * 8;
        ldsm_x4(smem_u32(&sK[row * 72 + col]), qf[ks][0], qf[ks][1], qf[ks][2], qf[ks][3]);
    }
    __syncthreads();   // Q frags extracted; stages may be overwritten

    float O[8][4];
#pragma unroll
    for (int t = 0; t < 8; ++t)
#pragma unroll
        for (int i = 0; i < 4; ++i) O[t][i] = 0.f;

    float l0 = 0.f, l1 = 0.f;

    const int ci = lane & 3;
    const int rl0 = rw + (lane >> 2);
    const int r0g = q0 + rl0;
    const size_t adjb0 = ((size_t)h * NN + r0g) * NN;
    const size_t adjb1 = adjb0 + 8 * (size_t)NN;

    // prologue: async-load tiles 0 and 1 into stages 0, 1
#pragma unroll
    for (int pre = 0; pre < 2; ++pre) {
        __nv_bfloat16* sKs = sK + pre * 64 * 72;
        __nv_bfloat16* sVs = sV + pre * 64 * 72;
#pragma unroll
        for (int p = 0; p < 2; ++p) {
            const int r = lr + p * 32;
            cp16(&sKs[r * 72 + lc8], g_K + (size_t)(pre * 64 + r) * FF + hc + lc8);
            cp16(&sVs[r * 72 + lc8], g_V + (size_t)(pre * 64 + r) * FF + hc + lc8);
        }
        cp_commit();
    }

    for (int jt = 0; jt < 64; ++jt) {
        const int stg = jt & 3;
        const int j0 = jt * 64;

        if (jt < 62) {
            const int j2 = (jt + 2) * 64;
            const int ns = (jt + 2) & 3;
            __nv_bfloat16* sKs = sK + ns * 64 * 72;
            __nv_bfloat16* sVs = sV + ns * 64 * 72;
#pragma unroll
            for (int p = 0; p < 2; ++p) {
                const int r = lr + p * 32;
                cp16(&sKs[r * 72 + lc8], g_K + (size_t)(j2 + r) * FF + hc + lc8);
                cp16(&sVs[r * 72 + lc8], g_V + (size_t)(j2 + r) * FF + hc + lc8);
            }
            cp_commit();
            cp_wait<2>();
        } else if (jt == 62) {
            cp_wait<1>();
        } else {
            cp_wait<0>();
        }
        __syncthreads();   // the ONLY barrier in the tile

        const __nv_bfloat16* sKc = sK + stg * 64 * 72;
        const __nv_bfloat16* sVc = sV + stg * 64 * 72;
        const int2* A0 = (const int2*)(adj + adjb0 + j0);
        const int2* A1 = (const int2*)(adj + adjb1 + j0);

        // ---- issue adj half0 (n cols 0..31) early ----
        int2 a0[4], a1[4];
#pragma unroll
        for (int t = 0; t < 4; ++t) {
            a0[t] = A0[t * 4 + ci];
            a1[t] = A1[t * 4 + ci];
        }

        uint32_t pk2[16];
        float s[4][4];

        // ---- S half0: n groups g=0,1 ----
#pragma unroll
        for (int t = 0; t < 4; ++t)
#pragma unroll
            for (int i = 0; i < 4; ++i) s[t][i] = 0.f;
#pragma unroll
        for (int ks = 0; ks < 4; ++ks) {
#pragma unroll
            for (int g = 0; g < 2; ++g) {
                const int row = g * 16 + (lane & 7) + (lane >> 4) * 8;
                const int col = ks * 16 + ((lane >> 3) & 1) * 8;
                uint32_t b0, b1, b2, b3;
                ldsm_x4(smem_u32(&sKc[row * 72 + col]), b0, b1, b2, b3);
                mma16816(s[2 * g],     qf[ks], b0, b1);
                mma16816(s[2 * g + 1], qf[ks], b2, b3);
            }
        }

        // ---- issue adj half1 (n cols 32..63) while half0 masks ----
        int2 c0[4], c1[4];
#pragma unroll
        for (int t = 0; t < 4; ++t) {
            c0[t] = A0[16 + t * 4 + ci];
            c1[t] = A1[16 + t * 4 + ci];
        }

        // ---- mask + exp half0 ----
#pragma unroll
        for (int t = 0; t < 4; ++t) {
            float p00 = ex2(s[t][0]);
            float p01 = ex2(s[t][1]);
            float p10 = ex2(s[t][2]);
            float p11 = ex2(s[t][3]);
            p00 = (a0[t].x > 0) ? p00 : 0.f;
            p01 = (a0[t].y > 0) ? p01 : 0.f;
            p10 = (a1[t].x > 0) ? p10 : 0.f;
            p11 = (a1[t].y > 0) ? p11 : 0.f;
            l0 += p00 + p01;
            l1 += p10 + p11;
            pk2[2 * t]     = packbf(p00, p01);
            pk2[2 * t + 1] = packbf(p10, p11);
        }

        // ---- S half1: n groups g=2,3 ----
#pragma unroll
        for (int t = 0; t < 4; ++t)
#pragma unroll
            for (int i = 0; i < 4; ++i) s[t][i] = 0.f;
#pragma unroll
        for (int ks = 0; ks < 4; ++ks) {
#pragma unroll
            for (int g = 2; g < 4; ++g) {
                const int row = g * 16 + (lane & 7) + (lane >> 4) * 8;
                const int col = ks * 16 + ((lane >> 3) & 1) * 8;
                uint32_t b0, b1, b2, b3;
                ldsm_x4(smem_u32(&sKc[row * 72 + col]), b0, b1, b2, b3);
                mma16816(s[2 * (g - 2)],     qf[ks], b0, b1);
                mma16816(s[2 * (g - 2) + 1], qf[ks], b2, b3);
            }
        }

        // ---- mask + exp half1 ----
#pragma unroll
        for (int t = 0; t < 4; ++t) {
            float p00 = ex2(s[t][0]);
            float p01 = ex2(s[t][1]);
            float p10 = ex2(s[t][2]);
            float p11 = ex2(s[t][3]);
            p00 = (c0[t].x > 0) ? p00 : 0.f;
            p01 = (c0[t].y > 0) ? p01 : 0.f;
            p10 = (c1[t].x > 0) ? p10 : 0.f;
            p11 = (c1[t].y > 0) ? p11 : 0.f;
            l0 += p00 + p01;
            l1 += p10 + p11;
            pk2[8 + 2 * t]     = packbf(p00, p01);
            pk2[8 + 2 * t + 1] = packbf(p10, p11);
        }

        // ---- O += P @ V ----
#pragma unroll
        for (int kg = 0; kg < 4; ++kg) {
            uint32_t pa[4];
            pa[0] = pk2[4 * kg];
            pa[1] = pk2[4 * kg + 1];
            pa[2] = pk2[4 * kg + 2];
            pa[3] = pk2[4 * kg + 3];
#pragma unroll
            for (int dg = 0; dg < 4; ++dg) {
                const int row = kg * 16 + (lane & 7) + ((lane >> 3) & 1) * 8;
                const int col = dg * 16 + (lane >> 4) * 8;
                uint32_t b0, b1, b2, b3;
                ldsm_x4_t(smem_u32(&sVc[row * 72 + col]), b0, b1, b2, b3);
                mma16816(O[2 * dg],     pa, b0, b1);
                mma16816(O[2 * dg + 1], pa, b2, b3);
            }
        }
        // no trailing barrier: 4-stage ring makes it unnecessary
    }

    // reduce l over the quad, then epilogue: normalize, residual, ELU
    l0 += __shfl_xor_sync(0xffffffffu, l0, 1);
    l0 += __shfl_xor_sync(0xffffffffu, l0, 2);
    l1 += __shfl_xor_sync(0xffffffffu, l1, 1);
    l1 += __shfl_xor_sync(0xffffffffu, l1, 2);
    const float inv0 = 1.f / l0;
    const float inv1 = 1.f / l1;
    const int r0 = r0g;
    const int r1 = r0 + 8;
#pragma unroll
    for (int t = 0; t < 8; ++t) {
        const int col = hc + t * 8 + ci * 2;
        float2 x0 = *(const float2*)(x + (size_t)r0 * FF + col);
        float2 x1 = *(const float2*)(x + (size_t)r1 * FF + col);
        float v00 = O[t][0] * inv0 + x0.x;
        float v01 = O[t][1] * inv0 + x0.y;
        float v10 = O[t][2] * inv1 + x1.x;
        float v11 = O[t][3] * inv1 + x1.y;
        v00 = (v00 > 0.f) ? v00 : expm1f(v00);
        v01 = (v01 > 0.f) ? v01 : expm1f(v01);
        v10 = (v10 > 0.f) ? v10 : expm1f(v10);
        v11 = (v11 > 0.f) ? v11 : expm1f(v11);
        *(float2*)(out + (size_t)r0 * FF + col) = make_float2(v00, v01);
        *(float2*)(out + (size_t)r1 * FF + col) = make_float2(v10, v11);
    }
}

extern "C" void kernel_launch(void* const* d_in, const int* in_sizes, int n_in,
                              void* d_out, int out_size) {
    const float* x  = (const float*)d_in[0];
    const float* Wq = (const float*)d_in[1];
    const float* Wk = (const float*)d_in[2];
    const float* Wv = (const float*)d_in[3];
    const int* adj  = (const int*)d_in[4];
    float* out = (float*)d_out;

    cudaFuncSetAttribute(proj_kernel, cudaFuncAttributeMaxDynamicSharedMemorySize, PROJ_SMEM);
    cudaFuncSetAttribute(attn_kernel, cudaFuncAttributeMaxDynamicSharedMemorySize, ATTN_SMEM);

    cvt_kernel<<<2816, 256>>>(x, Wq, Wk, Wv);
    proj_kernel<<<dim3(32, 12), 256, PROJ_SMEM>>>();
    attn_kernel<<<dim3(32, 8), 256, ATTN_SMEM>>>(x, adj, out);
}